// round 5
// baseline (speedup 1.0000x reference)
#include <cuda_runtime.h>
#include <cuda_bf16.h>
#include <cstdint>
#include <cfloat>

#define EPS    1e-12f
#define N_     8192
#define F_     512
#define D_     64
#define C_     8192
#define CAP    64
#define MARGIN 0.02f

// ---------------- device scratch ----------------
__device__ __align__(16) float g_zn[N_ * D_];
__device__ __align__(16) float g_cn[C_ * D_];
__device__ __align__(16) float g_csq[C_];
__device__ unsigned long long g_best[N_];
__device__ float g_rowloss[N_];
__device__ float g_dump[N_ + 1];
__device__ __align__(16) __nv_bfloat16 g_zb[N_ * D_];   // RN bf16 of zn
__device__ __align__(16) __nv_bfloat16 g_cb[C_ * D_];   // RN bf16 of cn
__device__ int g_cnt[N_];                               // candidate counters
__device__ unsigned short g_cand[N_ * CAP];             // candidate code idxs

__device__ __forceinline__ float warp_sum(float v) {
    #pragma unroll
    for (int o = 16; o; o >>= 1) v += __shfl_xor_sync(0xffffffffu, v, o);
    return v;
}
__device__ __forceinline__ uint32_t smem_to_u32(const void* p) {
    uint32_t a;
    asm("{ .reg .u64 t; cvta.to.shared.u64 t, %1; cvt.u32.u64 %0, t; }" : "=r"(a) : "l"(p));
    return a;
}
__device__ __forceinline__ void cp16(uint32_t dst, const void* src) {
    asm volatile("cp.async.cg.shared.global [%0], [%1], 16;" :: "r"(dst), "l"(src));
}
#define CP_COMMIT() asm volatile("cp.async.commit_group;" ::: "memory")
#define CP_WAIT1()  asm volatile("cp.async.wait_group 1;" ::: "memory")
#define CP_WAIT0()  asm volatile("cp.async.wait_group 0;" ::: "memory")

__device__ __forceinline__ void ldsm4(uint32_t* r, uint32_t addr) {
    asm volatile("ldmatrix.sync.aligned.m8n8.x4.shared.b16 {%0,%1,%2,%3}, [%4];"
                 : "=r"(r[0]), "=r"(r[1]), "=r"(r[2]), "=r"(r[3]) : "r"(addr));
}
__device__ __forceinline__ void mma16816(float* c, const uint32_t* a,
                                         uint32_t b0, uint32_t b1) {
    asm volatile("mma.sync.aligned.m16n8k16.row.col.f32.bf16.bf16.f32 "
                 "{%0,%1,%2,%3}, {%4,%5,%6,%7}, {%8,%9}, {%0,%1,%2,%3};"
                 : "+f"(c[0]), "+f"(c[1]), "+f"(c[2]), "+f"(c[3])
                 : "r"(a[0]), "r"(a[1]), "r"(a[2]), "r"(a[3]), "r"(b0), "r"(b1));
}
#define SWZ(o) ((o) ^ (((o) >> 3) & 0x70))

// ---------------- kernel 1: zn = normalise(z @ W_in + b_in) ----------------
__global__ void __launch_bounds__(512) k_zn(const float* __restrict__ z,
                                            const float* __restrict__ Win,
                                            const float* __restrict__ bin) {
    __shared__ float zs[16][F_];
    int w = threadIdx.x >> 5, lane = threadIdx.x & 31;
    int row = blockIdx.x * 16 + w;
    float* zr = zs[w];
    const float* zg = z + (size_t)row * F_;
    for (int k = lane; k < F_; k += 32) zr[k] = zg[k];
    __syncwarp();

    float a0 = bin[lane], a1 = bin[lane + 32];
    #pragma unroll 8
    for (int k = 0; k < F_; k++) {
        float zv = zr[k];
        a0 = fmaf(zv, Win[k * D_ + lane],      a0);
        a1 = fmaf(zv, Win[k * D_ + lane + 32], a1);
    }
    float s = warp_sum(a0 * a0 + a1 * a1);
    float r = rsqrtf(s * (1.0f / D_) + EPS);
    float zn0 = a0 * r, zn1 = a1 * r;
    g_zn[row * D_ + lane]      = zn0;
    g_zn[row * D_ + lane + 32] = zn1;
    g_zb[row * D_ + lane]      = __float2bfloat16_rn(zn0);
    g_zb[row * D_ + lane + 32] = __float2bfloat16_rn(zn1);
}

// ---------------- kernel 2: cn + csq ----------------
__global__ void __launch_bounds__(256) k_cn(const float* __restrict__ cb) {
    int w = threadIdx.x >> 5, lane = threadIdx.x & 31;
    int row = blockIdx.x * 8 + w;
    float v0 = cb[row * D_ + lane], v1 = cb[row * D_ + lane + 32];
    float s = warp_sum(v0 * v0 + v1 * v1);
    float r = rsqrtf(s * (1.0f / D_) + EPS);
    float c0 = v0 * r, c1 = v1 * r;
    g_cn[row * D_ + lane]      = c0;
    g_cn[row * D_ + lane + 32] = c1;
    float cs = warp_sum(c0 * c0 + c1 * c1);
    if (lane == 0) g_csq[row] = cs;
    g_cb[row * D_ + lane]      = __float2bfloat16_rn(c0);
    g_cb[row * D_ + lane + 32] = __float2bfloat16_rn(c1);
}

// ---------------- kernel 3: reset candidate counters (every replay) --------
__global__ void k_init() {
    int i = blockIdx.x * blockDim.x + threadIdx.x;
    if (i < N_) g_cnt[i] = 0;
}

// ---------------- kernel 4: bf16 HMMA approx distances + candidate record --
// CTA: 128 rows x 2048 cols, 32 chunks of 64 cols. 8 warps; warp w owns rows
// w*16..w*16+15. Record col if d < local_best + MARGIN (true argmin provably
// recorded: local_best >= row min; bf16 noise 20 sigma below MARGIN).
#define OFF_A    0            // 128 x 128B = 16KB
#define OFF_B    16384        // 2 bufs x 64 x 128B = 16KB
#define OFF_CSQ  32768        // 2 x 64 floats
#define DIST_SMEM 33280

__device__ __forceinline__ void rec(int row, int idx) {
    int slot = atomicAdd(&g_cnt[row], 1);
    if (slot < CAP) g_cand[row * CAP + slot] = (unsigned short)idx;
}

__device__ __forceinline__ void issue_B(uint32_t sb, int chunk, int buf,
                                        int c0, int tid) {
    const char* src_base = (const char*)g_cb;
    int colbase = c0 + chunk * 64;
    #pragma unroll
    for (int it = 0; it < 2; it++) {
        int i = tid + it * 256;
        int row = i >> 3, seg = i & 7;
        const char* src = src_base + ((size_t)(colbase + row)) * 128 + seg * 16;
        uint32_t off = row * 128 + seg * 16;
        cp16(sb + OFF_B + buf * 8192 + SWZ(off), src);
    }
    if (tid < 16)
        cp16(sb + OFF_CSQ + buf * 256 + tid * 16,
             (const char*)g_csq + (size_t)(colbase + tid * 4) * 4);
}

__global__ void __launch_bounds__(256, 2) k_dist() {
    extern __shared__ char sm[];
    uint32_t sb = smem_to_u32(sm);
    const int tid = threadIdx.x, w = tid >> 5, lane = tid & 31;
    const int r0 = blockIdx.y * 128;
    const int c0 = blockIdx.x * 2048;

    // prologue: A rows + B chunk 0 + csq0
    {
        const char* src_base = (const char*)g_zb;
        #pragma unroll
        for (int it = 0; it < 4; it++) {
            int i = tid + it * 256;
            int row = i >> 3, seg = i & 7;
            const char* src = src_base + ((size_t)(r0 + row)) * 128 + seg * 16;
            uint32_t off = row * 128 + seg * 16;
            cp16(sb + OFF_A + SWZ(off), src);
        }
    }
    issue_B(sb, 0, 0, c0, tid);
    CP_COMMIT();
    CP_WAIT0();
    __syncthreads();

    // A fragments once: a_frag[kstep][4]
    uint32_t a_frag[4][4];
    {
        int ml = (lane & 7) + ((lane >> 3) & 1) * 8;
        int kb = ((lane >> 4) & 1) * 16;
        #pragma unroll
        for (int k = 0; k < 4; k++) {
            uint32_t off = (w * 16 + ml) * 128 + k * 32 + kb;
            ldsm4(a_frag[k], sb + OFF_A + SWZ(off));
        }
    }

    float best0 = FLT_MAX, best1 = FLT_MAX;
    const int row0 = r0 + w * 16 + (lane >> 2);
    const int row1 = row0 + 8;

    const int nl  = (lane & 7) + ((lane >> 4) & 1) * 8;
    const int kbl = ((lane >> 3) & 1) * 16;

    for (int c = 0; c < 32; c++) {
        int buf = c & 1;
        __syncthreads();
        if (c + 1 < 32) {
            issue_B(sb, c + 1, buf ^ 1, c0, tid);
            CP_COMMIT();
            CP_WAIT1();
        } else {
            CP_WAIT0();
        }
        __syncthreads();

        float acc[8][4];
        #pragma unroll
        for (int nt = 0; nt < 8; nt++)
            #pragma unroll
            for (int j = 0; j < 4; j++) acc[nt][j] = 0.0f;

        uint32_t bbase = sb + OFF_B + buf * 8192;
        #pragma unroll
        for (int k = 0; k < 4; k++) {
            #pragma unroll
            for (int np = 0; np < 4; np++) {
                uint32_t br[4];
                uint32_t off = (np * 16 + nl) * 128 + k * 32 + kbl;
                ldsm4(br, bbase + SWZ(off));
                mma16816(acc[np * 2],     a_frag[k], br[0], br[1]);
                mma16816(acc[np * 2 + 1], a_frag[k], br[2], br[3]);
            }
        }

        // epilogue: approx distance + candidate recording
        const float* cq = (const float*)(sm + OFF_CSQ + buf * 256);
        int gbase = c0 + c * 64;
        #pragma unroll
        for (int nt = 0; nt < 8; nt++) {
            int col = nt * 8 + (lane & 3) * 2;
            float cq0 = cq[col], cq1 = cq[col + 1];
            float d0 = fmaf(-2.0f, acc[nt][0], cq0);
            float d1 = fmaf(-2.0f, acc[nt][1], cq1);
            float d2 = fmaf(-2.0f, acc[nt][2], cq0);
            float d3 = fmaf(-2.0f, acc[nt][3], cq1);
            if (d0 < best0 + MARGIN) rec(row0, gbase + col);
            if (d0 < best0) best0 = d0;
            if (d1 < best0 + MARGIN) rec(row0, gbase + col + 1);
            if (d1 < best0) best0 = d1;
            if (d2 < best1 + MARGIN) rec(row1, gbase + col);
            if (d2 < best1) best1 = d2;
            if (d3 < best1 + MARGIN) rec(row1, gbase + col + 1);
            if (d3 < best1) best1 = d3;
        }
    }
}

// ---------------- kernel 5: exact fp32 refine over candidates --------------
__global__ void __launch_bounds__(256) k_ref() {
    __shared__ float zs[8][D_];
    int w = threadIdx.x >> 5, lane = threadIdx.x & 31;
    int row = blockIdx.x * 8 + w;

    float z0 = g_zn[row * D_ + lane], z1 = g_zn[row * D_ + lane + 32];
    zs[w][lane] = z0;
    zs[w][lane + 32] = z1;
    __syncwarp();

    int n = g_cnt[row];
    unsigned long long best = 0xFFFFFFFFFFFFFFFFULL;

    if (n <= CAP) {
        for (int t = 0; t < n; t++) {
            int idx = g_cand[row * CAP + t];
            float c0 = g_cn[(size_t)idx * D_ + lane];
            float c1 = g_cn[(size_t)idx * D_ + lane + 32];
            float dot = warp_sum(z0 * c0 + z1 * c1);
            float d = fmaf(-2.0f, dot, g_csq[idx]);
            unsigned int kb = __float_as_uint(d);
            kb = (kb & 0x80000000u) ? ~kb : (kb | 0x80000000u);
            unsigned long long p = ((unsigned long long)kb << 32) | (unsigned int)idx;
            if (p < best) best = p;
        }
    } else {
        // overflow fallback: full exact scan (rare)
        for (int idx = lane; idx < C_; idx += 32) {
            float dot = 0.0f;
            const float* cr = g_cn + (size_t)idx * D_;
            #pragma unroll 16
            for (int d = 0; d < D_; d++) dot = fmaf(zs[w][d], cr[d], dot);
            float dd = fmaf(-2.0f, dot, g_csq[idx]);
            unsigned int kb = __float_as_uint(dd);
            kb = (kb & 0x80000000u) ? ~kb : (kb | 0x80000000u);
            unsigned long long p = ((unsigned long long)kb << 32) | (unsigned int)idx;
            if (p < best) best = p;
        }
        #pragma unroll
        for (int o = 16; o; o >>= 1) {
            unsigned long long q = __shfl_xor_sync(0xffffffffu, best, o);
            if (q < best) best = q;
        }
    }
    if (lane == 0) g_best[row] = best;
}

// ---------------- kernel 6: gather codes, out = codes@W_out, row loss ------
__global__ void __launch_bounds__(512) k_out(const float* __restrict__ Wout,
                                             const float* __restrict__ bout,
                                             float* __restrict__ out,
                                             float* __restrict__ idxf) {
    __shared__ float cs[16][D_];
    int w = threadIdx.x >> 5, lane = threadIdx.x & 31;
    int row = blockIdx.x * 16 + w;

    unsigned int idx = (unsigned int)(g_best[row] & 0xffffffffu);
    float c0 = g_cn[(size_t)idx * D_ + lane];
    float c1 = g_cn[(size_t)idx * D_ + lane + 32];
    cs[w][lane] = c0;
    cs[w][lane + 32] = c1;
    float d0 = g_zn[row * D_ + lane]      - c0;
    float d1 = g_zn[row * D_ + lane + 32] - c1;
    float s = warp_sum(d0 * d0 + d1 * d1);
    if (lane == 0) { g_rowloss[row] = s; idxf[row] = (float)idx; }
    __syncwarp();

    const float4* W4 = (const float4*)Wout;   // [d][128 float4]
    const float4* b4 = (const float4*)bout;
    float4* o4 = (float4*)(out + (size_t)row * F_);
    #pragma unroll
    for (int g = 0; g < 4; g++) {
        int f4 = lane + g * 32;
        float4 acc = b4[f4];
        #pragma unroll 16
        for (int d = 0; d < D_; d++) {
            float4 wv = W4[d * 128 + f4];
            float v = cs[w][d];
            acc.x = fmaf(v, wv.x, acc.x);
            acc.y = fmaf(v, wv.y, acc.y);
            acc.z = fmaf(v, wv.z, acc.z);
            acc.w = fmaf(v, wv.w, acc.w);
        }
        o4[f4] = acc;
    }
}

// ---------------- kernel 7: deterministic final loss reduction -------------
__global__ void k_loss(float* __restrict__ out_loss) {
    __shared__ double red[256];
    double s = 0.0;
    for (int i = threadIdx.x; i < N_; i += 256) s += (double)g_rowloss[i];
    red[threadIdx.x] = s;
    __syncthreads();
    for (int o = 128; o; o >>= 1) {
        if (threadIdx.x < o) red[threadIdx.x] += red[threadIdx.x + o];
        __syncthreads();
    }
    if (threadIdx.x == 0)
        *out_loss = (float)(1.25 * red[0] / (double)((long long)N_ * D_));
}

// ---------------- launch ----------------
extern "C" void kernel_launch(void* const* d_in, const int* in_sizes, int n_in,
                              void* d_out, int out_size) {
    const float* z    = (const float*)d_in[0];
    const float* Win  = (const float*)d_in[1];
    const float* bin  = (const float*)d_in[2];
    const float* cb   = (const float*)d_in[3];
    const float* Wout = (const float*)d_in[4];
    const float* bout = (const float*)d_in[5];
    float* out = (float*)d_out;

    long long expected = (long long)N_ * F_ + 1 + N_;
    float* lossp;
    float* idxp;
    if ((long long)out_size >= expected) {
        lossp = out + (size_t)N_ * F_;
        idxp  = lossp + 1;
    } else {
        cudaGetSymbolAddress((void**)&lossp, g_dump);
        idxp = lossp + 1;
    }

    cudaFuncSetAttribute(k_dist, cudaFuncAttributeMaxDynamicSharedMemorySize, DIST_SMEM);

    k_cn  <<<C_ / 8, 256>>>(cb);
    k_zn  <<<N_ / 16, 512>>>(z, Win, bin);
    k_init<<<(N_ + 255) / 256, 256>>>();
    k_dist<<<dim3(4, N_ / 128), 256, DIST_SMEM>>>();
    k_ref <<<N_ / 8, 256>>>();
    k_out <<<N_ / 16, 512>>>(Wout, bout, out, idxp);
    k_loss<<<1, 256>>>(lossp);
}

// round 13
// speedup vs baseline: 1.2481x; 1.2481x over previous
#include <cuda_runtime.h>
#include <cuda_bf16.h>
#include <cstdint>
#include <cfloat>

#define EPS    1e-12f
#define N_     8192
#define F_     512
#define D_     64
#define C_     8192
#define CAP    96
#define MARGIN 3.0f
#define LB     6

// ---------------- device scratch ----------------
__device__ __align__(16) float g_zn[N_ * D_];
__device__ __align__(16) float g_cn[C_ * D_];
__device__ __align__(16) float g_csq[C_];
__device__ unsigned long long g_best[N_];
__device__ float g_rowloss[N_];
__device__ float g_dump[N_ + 1];
__device__ __align__(16) __nv_bfloat16 g_zb[N_ * D_];   // RN bf16 of zn
__device__ __align__(16) __nv_bfloat16 g_cb[C_ * D_];   // RN bf16 of cn
__device__ int g_cnt[N_];                               // candidate counters
__device__ unsigned short g_cand[N_ * CAP];             // candidate code idxs

__device__ __forceinline__ float warp_sum(float v) {
    #pragma unroll
    for (int o = 16; o; o >>= 1) v += __shfl_xor_sync(0xffffffffu, v, o);
    return v;
}
__device__ __forceinline__ uint32_t smem_to_u32(const void* p) {
    uint32_t a;
    asm("{ .reg .u64 t; cvta.to.shared.u64 t, %1; cvt.u32.u64 %0, t; }" : "=r"(a) : "l"(p));
    return a;
}
__device__ __forceinline__ void cp16(uint32_t dst, const void* src) {
    asm volatile("cp.async.cg.shared.global [%0], [%1], 16;" :: "r"(dst), "l"(src));
}
#define CP_COMMIT() asm volatile("cp.async.commit_group;" ::: "memory")
#define CP_WAIT1()  asm volatile("cp.async.wait_group 1;" ::: "memory")
#define CP_WAIT0()  asm volatile("cp.async.wait_group 0;" ::: "memory")

__device__ __forceinline__ void ldsm4(uint32_t* r, uint32_t addr) {
    asm volatile("ldmatrix.sync.aligned.m8n8.x4.shared.b16 {%0,%1,%2,%3}, [%4];"
                 : "=r"(r[0]), "=r"(r[1]), "=r"(r[2]), "=r"(r[3]) : "r"(addr));
}
__device__ __forceinline__ void mma16816(float* c, const uint32_t* a,
                                         uint32_t b0, uint32_t b1) {
    asm volatile("mma.sync.aligned.m16n8k16.row.col.f32.bf16.bf16.f32 "
                 "{%0,%1,%2,%3}, {%4,%5,%6,%7}, {%8,%9}, {%0,%1,%2,%3};"
                 : "+f"(c[0]), "+f"(c[1]), "+f"(c[2]), "+f"(c[3])
                 : "r"(a[0]), "r"(a[1]), "r"(a[2]), "r"(a[3]), "r"(b0), "r"(b1));
}
#define SWZ(o) ((o) ^ (((o) >> 3) & 0x70))

// ---------------- kernel 1: zn = normalise(z @ W_in + b_in) ----------------
__global__ void __launch_bounds__(512) k_zn(const float* __restrict__ z,
                                            const float* __restrict__ Win,
                                            const float* __restrict__ bin) {
    __shared__ float zs[16][F_];
    int w = threadIdx.x >> 5, lane = threadIdx.x & 31;
    int row = blockIdx.x * 16 + w;
    float* zr = zs[w];
    const float* zg = z + (size_t)row * F_;
    for (int k = lane; k < F_; k += 32) zr[k] = zg[k];
    __syncwarp();

    float a0 = bin[lane], a1 = bin[lane + 32];
    #pragma unroll 8
    for (int k = 0; k < F_; k++) {
        float zv = zr[k];
        a0 = fmaf(zv, Win[k * D_ + lane],      a0);
        a1 = fmaf(zv, Win[k * D_ + lane + 32], a1);
    }
    float s = warp_sum(a0 * a0 + a1 * a1);
    float r = rsqrtf(s * (1.0f / D_) + EPS);
    float zn0 = a0 * r, zn1 = a1 * r;
    g_zn[row * D_ + lane]      = zn0;
    g_zn[row * D_ + lane + 32] = zn1;
    g_zb[row * D_ + lane]      = __float2bfloat16_rn(zn0);
    g_zb[row * D_ + lane + 32] = __float2bfloat16_rn(zn1);
}

// ---------------- kernel 2: cn + csq ----------------
__global__ void __launch_bounds__(256) k_cn(const float* __restrict__ cb) {
    int w = threadIdx.x >> 5, lane = threadIdx.x & 31;
    int row = blockIdx.x * 8 + w;
    float v0 = cb[row * D_ + lane], v1 = cb[row * D_ + lane + 32];
    float s = warp_sum(v0 * v0 + v1 * v1);
    float r = rsqrtf(s * (1.0f / D_) + EPS);
    float c0 = v0 * r, c1 = v1 * r;
    g_cn[row * D_ + lane]      = c0;
    g_cn[row * D_ + lane + 32] = c1;
    float cs = warp_sum(c0 * c0 + c1 * c1);
    if (lane == 0) g_csq[row] = cs;
    g_cb[row * D_ + lane]      = __float2bfloat16_rn(c0);
    g_cb[row * D_ + lane + 32] = __float2bfloat16_rn(c1);
}

// ---------------- kernel 3: reset candidate counters (every replay) --------
__global__ void k_init() {
    int i = blockIdx.x * blockDim.x + threadIdx.x;
    if (i < N_) g_cnt[i] = 0;
}

// ---------------- kernel 4: bf16 HMMA approx distances + local candidates --
// NOTE SCALE: normalise() divides by RMS, so ||zn||=||cn||=sqrt(D)=8.
// Worst-case bf16 distance error E = 2 * (2*2^-8 * ||zn||*||cn||) = 1.0.
// Two-sided retention needs MARGIN > 2E = 2.0 -> MARGIN = 3.0 (50% headroom).
// True argmin is always flushed (or cnt poisoned -> exact fullscan that row).
#define OFF_A    0            // 128 x 128B = 16KB
#define OFF_B    16384        // 2 bufs x 64 x 128B = 16KB
#define OFF_CSQ  32768        // 2 x 64 floats
#define DIST_SMEM 33280

#define INSERT(cd, ci, nn, ov, bst, dv, ix) do {                               \
    if (dv < bst + MARGIN) {                                                   \
        if (nn == LB) {                                                        \
            int _m = 0;                                                        \
            _Pragma("unroll")                                                  \
            for (int _i = 0; _i < LB; _i++)                                    \
                if (cd[_i] < bst + MARGIN) { cd[_m] = cd[_i]; ci[_m] = ci[_i]; _m++; } \
            nn = _m;                                                           \
        }                                                                      \
        if (nn < LB) { cd[nn] = dv; ci[nn] = ix; nn++; } else ov = true;       \
    }                                                                          \
    if (dv < bst) bst = dv;                                                    \
} while (0)

__device__ __forceinline__ void issue_B(uint32_t sb, int chunk, int buf,
                                        int c0, int tid) {
    const char* src_base = (const char*)g_cb;
    int colbase = c0 + chunk * 64;
    #pragma unroll
    for (int it = 0; it < 2; it++) {
        int i = tid + it * 256;
        int row = i >> 3, seg = i & 7;
        const char* src = src_base + ((size_t)(colbase + row)) * 128 + seg * 16;
        uint32_t off = row * 128 + seg * 16;
        cp16(sb + OFF_B + buf * 8192 + SWZ(off), src);
    }
    if (tid < 16)
        cp16(sb + OFF_CSQ + buf * 256 + tid * 16,
             (const char*)g_csq + (size_t)(colbase + tid * 4) * 4);
}

__global__ void __launch_bounds__(256, 2) k_dist() {
    extern __shared__ char sm[];
    uint32_t sb = smem_to_u32(sm);
    const int tid = threadIdx.x, w = tid >> 5, lane = tid & 31;
    const int r0 = blockIdx.y * 128;
    const int c0 = blockIdx.x * 2048;

    // prologue: A rows + B chunk 0 + csq0
    {
        const char* src_base = (const char*)g_zb;
        #pragma unroll
        for (int it = 0; it < 4; it++) {
            int i = tid + it * 256;
            int row = i >> 3, seg = i & 7;
            const char* src = src_base + ((size_t)(r0 + row)) * 128 + seg * 16;
            uint32_t off = row * 128 + seg * 16;
            cp16(sb + OFF_A + SWZ(off), src);
        }
    }
    issue_B(sb, 0, 0, c0, tid);
    CP_COMMIT();
    CP_WAIT0();
    __syncthreads();

    // A fragments once: a_frag[kstep][4]
    uint32_t a_frag[4][4];
    {
        int ml = (lane & 7) + ((lane >> 3) & 1) * 8;
        int kb = ((lane >> 4) & 1) * 16;
        #pragma unroll
        for (int k = 0; k < 4; k++) {
            uint32_t off = (w * 16 + ml) * 128 + k * 32 + kb;
            ldsm4(a_frag[k], sb + OFF_A + SWZ(off));
        }
    }

    float best0 = FLT_MAX, best1 = FLT_MAX;
    float cd0[LB], cd1[LB];
    int   ci0[LB], ci1[LB];
    int   n0 = 0, n1 = 0;
    bool  ov0 = false, ov1 = false;
    const int row0 = r0 + w * 16 + (lane >> 2);
    const int row1 = row0 + 8;

    const int nl  = (lane & 7) + ((lane >> 4) & 1) * 8;
    const int kbl = ((lane >> 3) & 1) * 16;

    for (int c = 0; c < 32; c++) {
        int buf = c & 1;
        __syncthreads();
        if (c + 1 < 32) {
            issue_B(sb, c + 1, buf ^ 1, c0, tid);
            CP_COMMIT();
            CP_WAIT1();
        } else {
            CP_WAIT0();
        }
        __syncthreads();

        float acc[8][4];
        #pragma unroll
        for (int nt = 0; nt < 8; nt++)
            #pragma unroll
            for (int j = 0; j < 4; j++) acc[nt][j] = 0.0f;

        uint32_t bbase = sb + OFF_B + buf * 8192;
        #pragma unroll
        for (int k = 0; k < 4; k++) {
            #pragma unroll
            for (int np = 0; np < 4; np++) {
                uint32_t br[4];
                uint32_t off = (np * 16 + nl) * 128 + k * 32 + kbl;
                ldsm4(br, bbase + SWZ(off));
                mma16816(acc[np * 2],     a_frag[k], br[0], br[1]);
                mma16816(acc[np * 2 + 1], a_frag[k], br[2], br[3]);
            }
        }

        const float* cq = (const float*)(sm + OFF_CSQ + buf * 256);
        int gbase = c0 + c * 64;
        #pragma unroll
        for (int nt = 0; nt < 8; nt++) {
            int col = nt * 8 + (lane & 3) * 2;
            float cq0 = cq[col], cq1 = cq[col + 1];
            float d0 = fmaf(-2.0f, acc[nt][0], cq0);
            float d1 = fmaf(-2.0f, acc[nt][1], cq1);
            float d2 = fmaf(-2.0f, acc[nt][2], cq0);
            float d3 = fmaf(-2.0f, acc[nt][3], cq1);
            int gc = gbase + col;
            INSERT(cd0, ci0, n0, ov0, best0, d0, gc);
            INSERT(cd0, ci0, n0, ov0, best0, d1, gc + 1);
            INSERT(cd1, ci1, n1, ov1, best1, d2, gc);
            INSERT(cd1, ci1, n1, ov1, best1, d3, gc + 1);
        }
    }

    // flush: only entries within MARGIN of final local best
    if (ov0) atomicAdd(&g_cnt[row0], CAP + 1);
    else
        for (int i = 0; i < n0; i++)
            if (cd0[i] < best0 + MARGIN) {
                int s = atomicAdd(&g_cnt[row0], 1);
                if (s < CAP) g_cand[row0 * CAP + s] = (unsigned short)ci0[i];
            }
    if (ov1) atomicAdd(&g_cnt[row1], CAP + 1);
    else
        for (int i = 0; i < n1; i++)
            if (cd1[i] < best1 + MARGIN) {
                int s = atomicAdd(&g_cnt[row1], 1);
                if (s < CAP) g_cand[row1 * CAP + s] = (unsigned short)ci1[i];
            }
}

// ---------------- kernel 5: exact fp32 refine over candidates --------------
__global__ void __launch_bounds__(256) k_ref() {
    __shared__ float zs[8][D_];
    int w = threadIdx.x >> 5, lane = threadIdx.x & 31;
    int row = blockIdx.x * 8 + w;

    float z0 = g_zn[row * D_ + lane], z1 = g_zn[row * D_ + lane + 32];
    zs[w][lane] = z0;
    zs[w][lane + 32] = z1;
    __syncwarp();

    int n = g_cnt[row];
    unsigned long long best = 0xFFFFFFFFFFFFFFFFULL;

    if (n <= CAP) {
        for (int t = 0; t < n; t++) {
            int idx = g_cand[row * CAP + t];
            float c0 = g_cn[(size_t)idx * D_ + lane];
            float c1 = g_cn[(size_t)idx * D_ + lane + 32];
            float dot = warp_sum(z0 * c0 + z1 * c1);
            float d = fmaf(-2.0f, dot, g_csq[idx]);
            unsigned int kb = __float_as_uint(d);
            kb = (kb & 0x80000000u) ? ~kb : (kb | 0x80000000u);
            unsigned long long p = ((unsigned long long)kb << 32) | (unsigned int)idx;
            if (p < best) best = p;
        }
    } else {
        // overflow fallback: full exact scan (rare)
        for (int idx = lane; idx < C_; idx += 32) {
            float dot = 0.0f;
            const float* cr = g_cn + (size_t)idx * D_;
            #pragma unroll 16
            for (int d = 0; d < D_; d++) dot = fmaf(zs[w][d], cr[d], dot);
            float dd = fmaf(-2.0f, dot, g_csq[idx]);
            unsigned int kb = __float_as_uint(dd);
            kb = (kb & 0x80000000u) ? ~kb : (kb | 0x80000000u);
            unsigned long long p = ((unsigned long long)kb << 32) | (unsigned int)idx;
            if (p < best) best = p;
        }
        #pragma unroll
        for (int o = 16; o; o >>= 1) {
            unsigned long long q = __shfl_xor_sync(0xffffffffu, best, o);
            if (q < best) best = q;
        }
    }
    if (lane == 0) g_best[row] = best;
}

// ---------------- kernel 6: gather codes, out = codes@W_out, row loss ------
__global__ void __launch_bounds__(512) k_out(const float* __restrict__ Wout,
                                             const float* __restrict__ bout,
                                             float* __restrict__ out,
                                             float* __restrict__ idxf) {
    __shared__ float cs[16][D_];
    int w = threadIdx.x >> 5, lane = threadIdx.x & 31;
    int row = blockIdx.x * 16 + w;

    unsigned int idx = (unsigned int)(g_best[row] & 0xffffffffu);
    float c0 = g_cn[(size_t)idx * D_ + lane];
    float c1 = g_cn[(size_t)idx * D_ + lane + 32];
    cs[w][lane] = c0;
    cs[w][lane + 32] = c1;
    float d0 = g_zn[row * D_ + lane]      - c0;
    float d1 = g_zn[row * D_ + lane + 32] - c1;
    float s = warp_sum(d0 * d0 + d1 * d1);
    if (lane == 0) { g_rowloss[row] = s; idxf[row] = (float)idx; }
    __syncwarp();

    const float4* W4 = (const float4*)Wout;   // [d][128 float4]
    const float4* b4 = (const float4*)bout;
    float4* o4 = (float4*)(out + (size_t)row * F_);
    #pragma unroll
    for (int g = 0; g < 4; g++) {
        int f4 = lane + g * 32;
        float4 acc = b4[f4];
        #pragma unroll 16
        for (int d = 0; d < D_; d++) {
            float4 wv = W4[d * 128 + f4];
            float v = cs[w][d];
            acc.x = fmaf(v, wv.x, acc.x);
            acc.y = fmaf(v, wv.y, acc.y);
            acc.z = fmaf(v, wv.z, acc.z);
            acc.w = fmaf(v, wv.w, acc.w);
        }
        o4[f4] = acc;
    }
}

// ---------------- kernel 7: deterministic final loss reduction -------------
__global__ void k_loss(float* __restrict__ out_loss) {
    __shared__ double red[256];
    double s = 0.0;
    for (int i = threadIdx.x; i < N_; i += 256) s += (double)g_rowloss[i];
    red[threadIdx.x] = s;
    __syncthreads();
    for (int o = 128; o; o >>= 1) {
        if (threadIdx.x < o) red[threadIdx.x] += red[threadIdx.x + o];
        __syncthreads();
    }
    if (threadIdx.x == 0)
        *out_loss = (float)(1.25 * red[0] / (double)((long long)N_ * D_));
}

// ---------------- launch ----------------
extern "C" void kernel_launch(void* const* d_in, const int* in_sizes, int n_in,
                              void* d_out, int out_size) {
    const float* z    = (const float*)d_in[0];
    const float* Win  = (const float*)d_in[1];
    const float* bin  = (const float*)d_in[2];
    const float* cb   = (const float*)d_in[3];
    const float* Wout = (const float*)d_in[4];
    const float* bout = (const float*)d_in[5];
    float* out = (float*)d_out;

    long long expected = (long long)N_ * F_ + 1 + N_;
    float* lossp;
    float* idxp;
    if ((long long)out_size >= expected) {
        lossp = out + (size_t)N_ * F_;
        idxp  = lossp + 1;
    } else {
        cudaGetSymbolAddress((void**)&lossp, g_dump);
        idxp = lossp + 1;
    }

    cudaFuncSetAttribute(k_dist, cudaFuncAttributeMaxDynamicSharedMemorySize, DIST_SMEM);

    k_cn  <<<C_ / 8, 256>>>(cb);
    k_zn  <<<N_ / 16, 512>>>(z, Win, bin);
    k_init<<<(N_ + 255) / 256, 256>>>();
    k_dist<<<dim3(4, N_ / 128), 256, DIST_SMEM>>>();
    k_ref <<<N_ / 8, 256>>>();
    k_out <<<N_ / 16, 512>>>(Wout, bout, out, idxp);
    k_loss<<<1, 256>>>(lossp);
}

// round 17
// speedup vs baseline: 11.0569x; 8.8592x over previous
#include <cuda_runtime.h>
#include <cuda_bf16.h>
#include <cstdint>
#include <cfloat>

#define EPS     1e-12f
#define N_      8192
#define F_      512
#define D_      64
#define C_      8192
#define MARGIN2 2.5f

// ---------------- device scratch ----------------
__device__ __align__(16) float g_zn[N_ * D_];
__device__ __align__(16) float g_cn[C_ * D_];
__device__ __align__(16) float g_csq[C_];
__device__ unsigned long long g_best[N_];
__device__ float g_rowloss[N_];
__device__ float g_dump[N_ + 1];
__device__ __align__(16) __nv_bfloat16 g_zb[N_ * D_];   // RN bf16 of zn
__device__ __align__(16) __nv_bfloat16 g_cb[C_ * D_];   // RN bf16 of cn

__device__ __forceinline__ float warp_sum(float v) {
    #pragma unroll
    for (int o = 16; o; o >>= 1) v += __shfl_xor_sync(0xffffffffu, v, o);
    return v;
}
__device__ __forceinline__ uint32_t smem_to_u32(const void* p) {
    uint32_t a;
    asm("{ .reg .u64 t; cvta.to.shared.u64 t, %1; cvt.u32.u64 %0, t; }" : "=r"(a) : "l"(p));
    return a;
}
__device__ __forceinline__ void cp16(uint32_t dst, const void* src) {
    asm volatile("cp.async.cg.shared.global [%0], [%1], 16;" :: "r"(dst), "l"(src));
}
#define CP_COMMIT() asm volatile("cp.async.commit_group;" ::: "memory")
#define CP_WAIT1()  asm volatile("cp.async.wait_group 1;" ::: "memory")
#define CP_WAIT0()  asm volatile("cp.async.wait_group 0;" ::: "memory")

__device__ __forceinline__ void ldsm4(uint32_t* r, uint32_t addr) {
    asm volatile("ldmatrix.sync.aligned.m8n8.x4.shared.b16 {%0,%1,%2,%3}, [%4];"
                 : "=r"(r[0]), "=r"(r[1]), "=r"(r[2]), "=r"(r[3]) : "r"(addr));
}
__device__ __forceinline__ void mma16816(float* c, const uint32_t* a,
                                         uint32_t b0, uint32_t b1) {
    asm volatile("mma.sync.aligned.m16n8k16.row.col.f32.bf16.bf16.f32 "
                 "{%0,%1,%2,%3}, {%4,%5,%6,%7}, {%8,%9}, {%0,%1,%2,%3};"
                 : "+f"(c[0]), "+f"(c[1]), "+f"(c[2]), "+f"(c[3])
                 : "r"(a[0]), "r"(a[1]), "r"(a[2]), "r"(a[3]), "r"(b0), "r"(b1));
}
#define SWZ(o) ((o) ^ (((o) >> 3) & 0x70))

// monotone float<->uint order maps (handles negatives)
__device__ __forceinline__ uint32_t f2ord(float f) {
    uint32_t u = __float_as_uint(f);
    return (u & 0x80000000u) ? ~u : (u | 0x80000000u);
}
__device__ __forceinline__ float ord2f(uint32_t u) {
    uint32_t v = (u & 0x80000000u) ? (u ^ 0x80000000u) : ~u;
    return __uint_as_float(v);
}

// ---------------- kernel 1: zn = normalise(z @ W_in + b_in) ----------------
__global__ void __launch_bounds__(256) k_zn(const float* __restrict__ z,
                                            const float* __restrict__ Win,
                                            const float* __restrict__ bin) {
    __shared__ float zs[8][F_];
    int w = threadIdx.x >> 5, lane = threadIdx.x & 31;
    int row = blockIdx.x * 8 + w;
    float* zr = zs[w];
    const float* zg = z + (size_t)row * F_;
    for (int k = lane; k < F_; k += 32) zr[k] = zg[k];
    __syncwarp();

    float a0 = bin[lane], a1 = bin[lane + 32];
    #pragma unroll 8
    for (int k = 0; k < F_; k++) {
        float zv = zr[k];
        a0 = fmaf(zv, Win[k * D_ + lane],      a0);
        a1 = fmaf(zv, Win[k * D_ + lane + 32], a1);
    }
    float s = warp_sum(a0 * a0 + a1 * a1);
    float r = rsqrtf(s * (1.0f / D_) + EPS);
    float zn0 = a0 * r, zn1 = a1 * r;
    g_zn[row * D_ + lane]      = zn0;
    g_zn[row * D_ + lane + 32] = zn1;
    g_zb[row * D_ + lane]      = __float2bfloat16_rn(zn0);
    g_zb[row * D_ + lane + 32] = __float2bfloat16_rn(zn1);
}

// ---------------- kernel 2: cn + csq ----------------
__global__ void __launch_bounds__(256) k_cn(const float* __restrict__ cb) {
    int w = threadIdx.x >> 5, lane = threadIdx.x & 31;
    int row = blockIdx.x * 8 + w;
    float v0 = cb[row * D_ + lane], v1 = cb[row * D_ + lane + 32];
    float s = warp_sum(v0 * v0 + v1 * v1);
    float r = rsqrtf(s * (1.0f / D_) + EPS);
    float c0 = v0 * r, c1 = v1 * r;
    g_cn[row * D_ + lane]      = c0;
    g_cn[row * D_ + lane + 32] = c1;
    float cs = warp_sum(c0 * c0 + c1 * c1);
    if (lane == 0) g_csq[row] = cs;
    g_cb[row * D_ + lane]      = __float2bfloat16_rn(c0);
    g_cb[row * D_ + lane + 32] = __float2bfloat16_rn(c1);
}

// ---------------- kernel 3: reset argmin state (every replay) --------------
__global__ void k_init() {
    int i = blockIdx.x * blockDim.x + threadIdx.x;
    if (i < N_) g_best[i] = 0xFFFFFFFFFFFFFFFFULL;
}

// ---------------- kernel 4: bf16 HMMA + shared row-min + inline exact ------
// CTA: 128 rows x 2048 cols. 33 iterations (chunk 0 twice: first min-only to
// seed rb, last records). Record when approx d < rb[row] + 2.5:
// worst-case bf16 distance error E = 2*(2*2^-8*||zn||*||cn||) = 1.0
// (||zn||=||cn||=sqrt(D)=8); retention needs MARGIN > 2E = 2.0 -> 2.5.
// Recording thread computes EXACT fp32 distance and atomicMins packed
// (dist-bits, idx) into g_best. No candidate buffers, no fallback scan.
#define OFF_A    0            // 128 x 128B = 16KB
#define OFF_B    16384        // 2 bufs x 64 x 128B = 16KB
#define OFF_CSQ  32768        // 2 x 64 floats
#define OFF_RB   33280        // 128 x u32 (ordered row minima)
#define DIST_SMEM 33792

__device__ __forceinline__ void exact_rec(int grow, int idx) {
    const float4* zr = (const float4*)(g_zn + (size_t)grow * D_);
    const float4* cr = (const float4*)(g_cn + (size_t)idx * D_);
    float dot = 0.0f;
    #pragma unroll
    for (int q = 0; q < 16; q++) {
        float4 a = zr[q], b = cr[q];
        dot += a.x * b.x + a.y * b.y + a.z * b.z + a.w * b.w;
    }
    float d = fmaf(-2.0f, dot, g_csq[idx]);
    unsigned long long packed =
        ((unsigned long long)f2ord(d) << 32) | (unsigned int)idx;
    atomicMin(&g_best[grow], packed);
}

__device__ __forceinline__ void issue_B(uint32_t sb, int chunk, int buf,
                                        int c0, int tid) {
    const char* src_base = (const char*)g_cb;
    int colbase = c0 + chunk * 64;
    #pragma unroll
    for (int it = 0; it < 2; it++) {
        int i = tid + it * 256;
        int row = i >> 3, seg = i & 7;
        const char* src = src_base + ((size_t)(colbase + row)) * 128 + seg * 16;
        uint32_t off = row * 128 + seg * 16;
        cp16(sb + OFF_B + buf * 8192 + SWZ(off), src);
    }
    if (tid < 16)
        cp16(sb + OFF_CSQ + buf * 256 + tid * 16,
             (const char*)g_csq + (size_t)(colbase + tid * 4) * 4);
}

__global__ void __launch_bounds__(256, 2) k_dist() {
    extern __shared__ char sm[];
    uint32_t sb = smem_to_u32(sm);
    const int tid = threadIdx.x, w = tid >> 5, lane = tid & 31;
    const int r0 = blockIdx.y * 128;
    const int c0 = blockIdx.x * 2048;
    uint32_t* rb = (uint32_t*)(sm + OFF_RB);

    if (tid < 128) rb[tid] = 0xFFFFFFFFu;

    // prologue: A rows + B chunk 0 + csq0
    {
        const char* src_base = (const char*)g_zb;
        #pragma unroll
        for (int it = 0; it < 4; it++) {
            int i = tid + it * 256;
            int row = i >> 3, seg = i & 7;
            const char* src = src_base + ((size_t)(r0 + row)) * 128 + seg * 16;
            uint32_t off = row * 128 + seg * 16;
            cp16(sb + OFF_A + SWZ(off), src);
        }
    }
    issue_B(sb, 0, 0, c0, tid);
    CP_COMMIT();
    CP_WAIT0();
    __syncthreads();

    // A fragments once
    uint32_t a_frag[4][4];
    {
        int ml = (lane & 7) + ((lane >> 3) & 1) * 8;
        int kb = ((lane >> 4) & 1) * 16;
        #pragma unroll
        for (int k = 0; k < 4; k++) {
            uint32_t off = (w * 16 + ml) * 128 + k * 32 + kb;
            ldsm4(a_frag[k], sb + OFF_A + SWZ(off));
        }
    }

    const int lr0 = w * 16 + (lane >> 2);     // local row in [0,128)
    const int lr1 = lr0 + 8;
    const int grow0 = r0 + lr0, grow1 = r0 + lr1;
    float best0 = FLT_MAX, best1 = FLT_MAX;

    const int nl  = (lane & 7) + ((lane >> 4) & 1) * 8;
    const int kbl = ((lane >> 3) & 1) * 16;

    for (int it = 0; it <= 32; it++) {
        int buf = it & 1;
        int chunk = (it == 32) ? 0 : it;
        __syncthreads();
        if (it < 32) {
            int nxt = (it + 1 == 32) ? 0 : it + 1;
            issue_B(sb, nxt, buf ^ 1, c0, tid);
            CP_COMMIT();
            CP_WAIT1();
        } else {
            CP_WAIT0();
        }
        __syncthreads();

        float acc[8][4];
        #pragma unroll
        for (int nt = 0; nt < 8; nt++)
            #pragma unroll
            for (int j = 0; j < 4; j++) acc[nt][j] = 0.0f;

        uint32_t bbase = sb + OFF_B + buf * 8192;
        #pragma unroll
        for (int k = 0; k < 4; k++) {
            #pragma unroll
            for (int np = 0; np < 4; np++) {
                uint32_t br[4];
                uint32_t off = (np * 16 + nl) * 128 + k * 32 + kbl;
                ldsm4(br, bbase + SWZ(off));
                mma16816(acc[np * 2],     a_frag[k], br[0], br[1]);
                mma16816(acc[np * 2 + 1], a_frag[k], br[2], br[3]);
            }
        }

        // epilogue
        const float* cq = (const float*)(sm + OFF_CSQ + buf * 256);
        int gbase = c0 + chunk * 64;
        float th0 = -FLT_MAX, th1 = -FLT_MAX;
        if (it >= 1) {
            th0 = ord2f(rb[lr0]) + MARGIN2;
            th1 = ord2f(rb[lr1]) + MARGIN2;
        }
        #pragma unroll
        for (int nt = 0; nt < 8; nt++) {
            int col = nt * 8 + (lane & 3) * 2;
            float cq0 = cq[col], cq1 = cq[col + 1];
            float d0 = fmaf(-2.0f, acc[nt][0], cq0);
            float d1 = fmaf(-2.0f, acc[nt][1], cq1);
            float d2 = fmaf(-2.0f, acc[nt][2], cq0);
            float d3 = fmaf(-2.0f, acc[nt][3], cq1);
            if (d0 < best0) best0 = d0;
            if (d1 < best0) best0 = d1;
            if (d2 < best1) best1 = d2;
            if (d3 < best1) best1 = d3;
            if (it >= 1) {
                int gc = gbase + col;
                if (d0 < th0) exact_rec(grow0, gc);
                if (d1 < th0) exact_rec(grow0, gc + 1);
                if (d2 < th1) exact_rec(grow1, gc);
                if (d3 < th1) exact_rec(grow1, gc + 1);
            }
        }
        // publish running minima (visible next iteration after syncthreads)
        atomicMin(&rb[lr0], f2ord(best0));
        atomicMin(&rb[lr1], f2ord(best1));
    }
}

// ---------------- kernel 5: gather codes, out = codes@W_out, row loss ------
__global__ void __launch_bounds__(256) k_out(const float* __restrict__ Wout,
                                             const float* __restrict__ bout,
                                             float* __restrict__ out,
                                             float* __restrict__ idxf) {
    __shared__ float cs[8][D_];
    int w = threadIdx.x >> 5, lane = threadIdx.x & 31;
    int row = blockIdx.x * 8 + w;

    unsigned int idx = (unsigned int)(g_best[row] & 0xffffffffu);
    float c0 = g_cn[(size_t)idx * D_ + lane];
    float c1 = g_cn[(size_t)idx * D_ + lane + 32];
    cs[w][lane] = c0;
    cs[w][lane + 32] = c1;
    float d0 = g_zn[row * D_ + lane]      - c0;
    float d1 = g_zn[row * D_ + lane + 32] - c1;
    float s = warp_sum(d0 * d0 + d1 * d1);
    if (lane == 0) { g_rowloss[row] = s; idxf[row] = (float)idx; }
    __syncwarp();

    const float4* W4 = (const float4*)Wout;   // [d][128 float4]
    const float4* b4 = (const float4*)bout;
    float4* o4 = (float4*)(out + (size_t)row * F_);
    #pragma unroll
    for (int g = 0; g < 4; g++) {
        int f4 = lane + g * 32;
        float4 acc = b4[f4];
        #pragma unroll 16
        for (int d = 0; d < D_; d++) {
            float4 wv = W4[d * 128 + f4];
            float v = cs[w][d];
            acc.x = fmaf(v, wv.x, acc.x);
            acc.y = fmaf(v, wv.y, acc.y);
            acc.z = fmaf(v, wv.z, acc.z);
            acc.w = fmaf(v, wv.w, acc.w);
        }
        o4[f4] = acc;
    }
}

// ---------------- kernel 6: deterministic final loss reduction -------------
__global__ void k_loss(float* __restrict__ out_loss) {
    __shared__ double red[256];
    double s = 0.0;
    for (int i = threadIdx.x; i < N_; i += 256) s += (double)g_rowloss[i];
    red[threadIdx.x] = s;
    __syncthreads();
    for (int o = 128; o; o >>= 1) {
        if (threadIdx.x < o) red[threadIdx.x] += red[threadIdx.x + o];
        __syncthreads();
    }
    if (threadIdx.x == 0)
        *out_loss = (float)(1.25 * red[0] / (double)((long long)N_ * D_));
}

// ---------------- launch ----------------
extern "C" void kernel_launch(void* const* d_in, const int* in_sizes, int n_in,
                              void* d_out, int out_size) {
    const float* z    = (const float*)d_in[0];
    const float* Win  = (const float*)d_in[1];
    const float* bin  = (const float*)d_in[2];
    const float* cb   = (const float*)d_in[3];
    const float* Wout = (const float*)d_in[4];
    const float* bout = (const float*)d_in[5];
    float* out = (float*)d_out;

    long long expected = (long long)N_ * F_ + 1 + N_;
    float* lossp;
    float* idxp;
    if ((long long)out_size >= expected) {
        lossp = out + (size_t)N_ * F_;
        idxp  = lossp + 1;
    } else {
        cudaGetSymbolAddress((void**)&lossp, g_dump);
        idxp = lossp + 1;
    }

    cudaFuncSetAttribute(k_dist, cudaFuncAttributeMaxDynamicSharedMemorySize, DIST_SMEM);

    k_cn  <<<C_ / 8, 256>>>(cb);
    k_zn  <<<N_ / 8, 256>>>(z, Win, bin);
    k_init<<<(N_ + 255) / 256, 256>>>();
    k_dist<<<dim3(4, N_ / 128), 256, DIST_SMEM>>>();
    k_out <<<N_ / 8, 256>>>(Wout, bout, out, idxp);
    k_loss<<<1, 256>>>(lossp);
}